// round 1
// baseline (speedup 1.0000x reference)
#include <cuda_runtime.h>
#include <math.h>

// Problem shapes (fixed by the dataset)
constexpr int NDIM  = 80;     // n_channels
constexpr int BATCH = 64;
constexpr int SEQ   = 1000;
constexpr int KST   = 12;     // n_states
constexpr int NBK   = BATCH * KST;   // 768
constexpr int ST    = 64;     // samples per tile in kernel B
constexpr int DS_STRIDE = 84; // float stride for diff tile (mult of 4, conflict-free for LDS.128)

constexpr float LOG_2PI = 1.837877066409345339082f;
constexpr float EPS = 1e-5f;

// Scratch: per-(b,k) inverse Cholesky factor (dense, zeros above diag) + logdet
__device__ float g_minv[(size_t)NBK * NDIM * NDIM];
__device__ float g_logdet[NBK];

// ---------------------------------------------------------------------------
// Kernel A: per (b,k) — Cholesky of sigma + eps*I, logdet(L), Minv = L^-1
// One block per matrix, 256 threads.
// ---------------------------------------------------------------------------
__global__ __launch_bounds__(256) void chol_inv_kernel(const float* __restrict__ sigma) {
    __shared__ float A[NDIM][NDIM + 1];
    const int bk  = blockIdx.x;
    const int tid = threadIdx.x;
    const float* Sg = sigma + (size_t)bk * NDIM * NDIM;

    // Load sigma + eps*I
    for (int idx = tid; idx < NDIM * NDIM; idx += 256) {
        int i = idx / NDIM, j = idx % NDIM;
        float v = Sg[idx];
        if (i == j) v += EPS;
        A[i][j] = v;
    }
    __syncthreads();

    // Right-looking Cholesky (lower)
    for (int k = 0; k < NDIM; ++k) {
        if (tid == 0) A[k][k] = sqrtf(A[k][k]);
        __syncthreads();
        float dinv = 1.0f / A[k][k];
        for (int i = k + 1 + tid; i < NDIM; i += 256) A[i][k] *= dinv;
        __syncthreads();
        int r = NDIM - 1 - k;
        for (int idx = tid; idx < r * r; idx += 256) {
            int i = k + 1 + idx / r;
            int j = k + 1 + idx % r;
            if (j <= i) A[i][j] -= A[i][k] * A[j][k];
        }
        __syncthreads();
    }

    if (tid == 0) {
        float s = 0.0f;
        for (int j = 0; j < NDIM; ++j) s += logf(A[j][j]);
        g_logdet[bk] = s;
    }

    // Triangular inverse: column c solved by thread c (forward substitution)
    float* out = g_minv + (size_t)bk * NDIM * NDIM;
    if (tid < NDIM) {
        const int c = tid;
        float col[NDIM];  // local-memory backed; accesses are coalesced across threads
        col[c] = 1.0f / A[c][c];
        for (int i = c + 1; i < NDIM; ++i) {
            float s0 = 0.0f, s1 = 0.0f;
            int j = c;
            for (; j + 1 < i; j += 2) {
                s0 = fmaf(A[i][j],     col[j],     s0);
                s1 = fmaf(A[i][j + 1], col[j + 1], s1);
            }
            for (; j < i; ++j) s0 = fmaf(A[i][j], col[j], s0);
            col[i] = -(s0 + s1) / A[i][i];
        }
        // Dense write with explicit zeros above the diagonal (kernel B relies on this)
        for (int i = 0; i < NDIM; ++i)
            out[i * NDIM + c] = (i >= c) ? col[i] : 0.0f;
    }
}

// ---------------------------------------------------------------------------
// Kernel B: fused z = Minv*diff, quad = |z|^2, ll. One block per
// (sample-tile, k, b). 256 threads = 4 groups x 64 samples.
// Group g handles rows i = g, g+4, ... (interleaved -> balanced triangular work).
// ---------------------------------------------------------------------------
__global__ __launch_bounds__(256) void ll_kernel(const float* __restrict__ x,
                                                 const float* __restrict__ mu,
                                                 float* __restrict__ out) {
    __shared__ __align__(16) float msh[NDIM * NDIM];         // Minv (25.6 KB)
    __shared__ __align__(16) float ds[ST * DS_STRIDE];       // diff tile (21.5 KB)
    __shared__ float mush[NDIM];

    const int s0 = blockIdx.x * ST;
    const int k  = blockIdx.y;
    const int b  = blockIdx.z;
    const int bk = b * KST + k;
    const int tid = threadIdx.x;

    // Stage Minv + mu
    const float* mv = g_minv + (size_t)bk * NDIM * NDIM;
    for (int idx = tid; idx < NDIM * NDIM; idx += 256) msh[idx] = mv[idx];
    if (tid < NDIM) mush[tid] = mu[(size_t)bk * NDIM + tid];
    __syncthreads();

    int navail = SEQ - s0;
    if (navail > ST) navail = ST;
    const float* xb = x + ((size_t)b * SEQ + s0) * NDIM;

    // Stage diff = x - mu, per-sample contiguous rows (stride 84 floats)
    for (int idx = tid; idx < ST * NDIM; idx += 256) {
        int s = idx / NDIM, n = idx % NDIM;
        ds[s * DS_STRIDE + n] = (s < navail) ? (xb[idx] - mush[n]) : 0.0f;
    }
    __syncthreads();

    const int sl = tid & (ST - 1);   // sample within tile
    const int g  = tid >> 6;         // row-group 0..3
    const float4* dv = reinterpret_cast<const float4*>(&ds[sl * DS_STRIDE]);

    float acc = 0.0f;
    for (int i = g; i < NDIM; i += 4) {
        const float4* row = reinterpret_cast<const float4*>(&msh[i * NDIM]);
        const int jn = (i >> 2) + 1;  // float4 chunks covering j <= i (pad terms hit zeros)
        float z0 = 0.f, z1 = 0.f, z2 = 0.f, z3 = 0.f;
        #pragma unroll 4
        for (int j = 0; j < jn; ++j) {
            float4 m4 = row[j];
            float4 d4 = dv[j];
            z0 = fmaf(m4.x, d4.x, z0);
            z1 = fmaf(m4.y, d4.y, z1);
            z2 = fmaf(m4.z, d4.z, z2);
            z3 = fmaf(m4.w, d4.w, z3);
        }
        float z = (z0 + z1) + (z2 + z3);
        acc = fmaf(z, z, acc);
    }

    // Cross-group reduction: reuse ds as scratch (all reads of ds are done)
    __syncthreads();
    float* part = ds;
    part[g * ST + sl] = acc;
    __syncthreads();

    if (g == 0 && sl < navail) {
        float q = part[sl] + part[ST + sl] + part[2 * ST + sl] + part[3 * ST + sl];
        float ll = -0.5f * q - g_logdet[bk] - 0.5f * (float)NDIM * LOG_2PI;
        out[((size_t)b * SEQ + s0 + sl) * KST + k] = ll;
    }
}

// ---------------------------------------------------------------------------
extern "C" void kernel_launch(void* const* d_in, const int* in_sizes, int n_in,
                              void* d_out, int out_size) {
    const float* x     = (const float*)d_in[0];
    const float* mu    = (const float*)d_in[1];
    const float* sigma = (const float*)d_in[2];
    float* out = (float*)d_out;

    chol_inv_kernel<<<NBK, 256>>>(sigma);

    dim3 grid((SEQ + ST - 1) / ST, KST, BATCH);
    ll_kernel<<<grid, 256>>>(x, mu, out);
}

// round 2
// speedup vs baseline: 1.4856x; 1.4856x over previous
#include <cuda_runtime.h>
#include <math.h>

// Problem shapes (fixed by the dataset)
constexpr int NDIM  = 80;
constexpr int BATCH = 64;
constexpr int SEQ   = 1000;
constexpr int KST   = 12;
constexpr int NBK   = BATCH * KST;   // 768
constexpr int ST    = 64;            // samples per tile in kernel B
constexpr int MST   = 82;            // msh row stride (8B-aligned pairs)
constexpr int DST   = 68;            // ds row stride

constexpr float LOG_2PI = 1.837877066409345339082f;
constexpr float EPS = 1e-5f;

// Scratch: per-(b,k) TRANSPOSED inverse Cholesky factor (minvT[j][i] = L^-1[i][j],
// dense with zeros where i<j) + logdet
__device__ float g_minvT[(size_t)NBK * NDIM * NDIM];
__device__ float g_logdet[NBK];

// ---------------------------------------------------------------------------
// f32x2 helpers (sm_103a packed fp32)
// ---------------------------------------------------------------------------
__device__ __forceinline__ unsigned long long fma2(unsigned long long a,
                                                   unsigned long long b,
                                                   unsigned long long c) {
    unsigned long long d;
    asm("fma.rn.f32x2 %0, %1, %2, %3;" : "=l"(d) : "l"(a), "l"(b), "l"(c));
    return d;
}
__device__ __forceinline__ unsigned long long dup2(float x) {
    unsigned long long d;
    asm("mov.b64 %0, {%1, %1};" : "=l"(d) : "f"(x));
    return d;
}
__device__ __forceinline__ void unpack2(unsigned long long v, float& lo, float& hi) {
    asm("mov.b64 {%0, %1}, %2;" : "=f"(lo), "=f"(hi) : "l"(v));
}

// ---------------------------------------------------------------------------
// Kernel A: per (b,k) — Cholesky of sigma + eps*I, logdet(L), in-place
// triangular inverse (dtrti2 ordering, j = N-1..0), store transposed + dense.
// ---------------------------------------------------------------------------
__global__ __launch_bounds__(256) void chol_inv_kernel(const float* __restrict__ sigma) {
    __shared__ float A[NDIM][NDIM + 1];
    __shared__ float colbuf[NDIM];
    const int bk  = blockIdx.x;
    const int tid = threadIdx.x;
    const float* Sg = sigma + (size_t)bk * NDIM * NDIM;

    // Load sigma + eps*I
    for (int idx = tid; idx < NDIM * NDIM; idx += 256) {
        int i = idx / NDIM, j = idx % NDIM;
        float v = Sg[idx];
        if (i == j) v += EPS;
        A[i][j] = v;
    }
    __syncthreads();

    // Right-looking Cholesky (lower)
    for (int k = 0; k < NDIM; ++k) {
        if (tid == 0) A[k][k] = sqrtf(A[k][k]);
        __syncthreads();
        float dinv = 1.0f / A[k][k];
        for (int i = k + 1 + tid; i < NDIM; i += 256) A[i][k] *= dinv;
        __syncthreads();
        int r = NDIM - 1 - k;
        for (int idx = tid; idx < r * r; idx += 256) {
            int i = k + 1 + idx / r;
            int j = k + 1 + idx % r;
            if (j <= i) A[i][j] -= A[i][k] * A[j][k];
        }
        __syncthreads();
    }

    // logdet before the diagonal is overwritten by the inverse
    if (tid < NDIM) colbuf[tid] = logf(A[tid][tid]);
    __syncthreads();
    if (tid == 0) {
        float s = 0.0f;
        for (int j = 0; j < NDIM; ++j) s += colbuf[j];
        g_logdet[bk] = s;
    }
    __syncthreads();

    // In-place lower-triangular inverse, columns right-to-left.
    // X[j][j] = 1/L[j][j];  X[i][j] = -(1/L[j][j]) * sum_{k=j+1..i} X[i][k]*L[k][j]
    // Trailing X[i][k] (k>j) already final; snapshot original column j first.
    for (int j = NDIM - 1; j >= 0; --j) {
        for (int i = j + 1 + tid; i < NDIM; i += 256) colbuf[i] = A[i][j];
        float ajj_inv = 1.0f / A[j][j];
        __syncthreads();
        if (tid == 0) A[j][j] = ajj_inv;
        for (int i = j + 1 + tid; i < NDIM; i += 256) {
            float s0 = 0.0f, s1 = 0.0f;
            int k = j + 1;
            for (; k + 1 <= i; k += 2) {
                s0 = fmaf(A[i][k],     colbuf[k],     s0);
                s1 = fmaf(A[i][k + 1], colbuf[k + 1], s1);
            }
            if (k <= i) s0 = fmaf(A[i][k], colbuf[k], s0);
            A[i][j] = -ajj_inv * (s0 + s1);
        }
        __syncthreads();
    }

    // Store transposed + dense zeros: g_minvT[bk][j][i] = (i>=j) ? X[i][j] : 0
    float* out = g_minvT + (size_t)bk * NDIM * NDIM;
    for (int idx = tid; idx < NDIM * NDIM; idx += 256) {
        int j = idx / NDIM, i = idx % NDIM;
        out[idx] = (i >= j) ? A[i][j] : 0.0f;
    }
}

// ---------------------------------------------------------------------------
// Kernel B: fused z = Minv*diff, quad = |z|^2, ll.
// Block = 320 threads = 20 row-groups (ty, 4 rows each) x 16 sample-groups
// (tx, 4 samples each). One block per (64-sample tile, k, b).
// MinvT in shared as [j][i] (row-pairs -> LDS.64); diff as [n][s] (-> LDS.128).
// Inner loop: 8 x fma.rn.f32x2 per j-step.
// ---------------------------------------------------------------------------
__global__ __launch_bounds__(320) void ll_kernel(const float* __restrict__ x,
                                                 const float* __restrict__ mu,
                                                 float* __restrict__ out) {
    __shared__ __align__(16) float msh[NDIM * MST];  // 26240 B
    __shared__ __align__(16) float ds[NDIM * DST];   // 21760 B

    const int tid = threadIdx.x;
    const int tx  = tid & 15;   // sample group
    const int ty  = tid >> 4;   // row group 0..19
    const int s0  = blockIdx.x * ST;
    const int k   = blockIdx.y;
    const int b   = blockIdx.z;
    const int bk  = b * KST + k;

    // Stage MinvT
    const float* mv = g_minvT + (size_t)bk * NDIM * NDIM;
    for (int idx = tid; idx < NDIM * NDIM; idx += 320) {
        int j = idx / NDIM, i = idx % NDIM;
        msh[j * MST + i] = mv[idx];
    }

    // Stage diff transposed: ds[n][s] = x[b][s0+s][n] - mu[bk][n]
    int navail = SEQ - s0; if (navail > ST) navail = ST;
    const float* xb  = x  + ((size_t)b * SEQ + s0) * NDIM;
    const float* mub = mu + (size_t)bk * NDIM;
    for (int idx = tid; idx < ST * NDIM; idx += 320) {
        int s = idx / NDIM, n = idx % NDIM;
        float v = 0.0f;
        if (s < navail) v = xb[idx] - __ldg(mub + n);
        ds[n * DST + s] = v;
    }
    __syncthreads();

    // Mainloop: rows i = 4*ty .. 4*ty+3 (two f32x2 pairs), samples 4*tx .. 4*tx+3
    unsigned long long acc[8];
    #pragma unroll
    for (int u = 0; u < 8; ++u) acc[u] = 0ULL;

    const int jmax = 4 * ty + 4;  // zeros above diagonal cover in-group rows
    const float* mrow = msh + 4 * ty;
    const float* drow = ds + 4 * tx;

    #pragma unroll 2
    for (int j = 0; j < jmax; ++j) {
        unsigned long long m0 = *reinterpret_cast<const unsigned long long*>(mrow);      // rows 4ty,4ty+1
        unsigned long long m1 = *reinterpret_cast<const unsigned long long*>(mrow + 2);  // rows 4ty+2,4ty+3
        float4 d4 = *reinterpret_cast<const float4*>(drow);
        unsigned long long dx = dup2(d4.x), dy = dup2(d4.y), dz = dup2(d4.z), dw = dup2(d4.w);
        acc[0] = fma2(m0, dx, acc[0]);
        acc[1] = fma2(m0, dy, acc[1]);
        acc[2] = fma2(m0, dz, acc[2]);
        acc[3] = fma2(m0, dw, acc[3]);
        acc[4] = fma2(m1, dx, acc[4]);
        acc[5] = fma2(m1, dy, acc[5]);
        acc[6] = fma2(m1, dz, acc[6]);
        acc[7] = fma2(m1, dw, acc[7]);
        mrow += MST;
        drow += DST;
    }

    // Per-thread quad partial per sample: sum over this thread's 4 rows of z^2
    float4 q;
    {
        float a, bb, c, d, e, f, g, h;
        unpack2(acc[0], a, bb); unpack2(acc[4], c, d);
        q.x = a * a + bb * bb + c * c + d * d;
        unpack2(acc[1], a, bb); unpack2(acc[5], c, d);
        q.y = a * a + bb * bb + c * c + d * d;
        unpack2(acc[2], a, bb); unpack2(acc[6], c, d);
        q.z = a * a + bb * bb + c * c + d * d;
        unpack2(acc[3], e, f);  unpack2(acc[7], g, h);
        q.w = e * e + f * f + g * g + h * h;
    }

    __syncthreads();  // all reads of ds done -> reuse as reduction scratch
    *reinterpret_cast<float4*>(&ds[ty * DST + 4 * tx]) = q;
    __syncthreads();

    // Final reduce across the 20 row groups, one thread per sample
    if (tid < ST && tid < navail) {
        float sum = 0.0f;
        #pragma unroll
        for (int t = 0; t < 20; ++t) sum += ds[t * DST + tid];
        float ll = -0.5f * sum - g_logdet[bk] - 0.5f * (float)NDIM * LOG_2PI;
        out[((size_t)b * SEQ + s0 + tid) * KST + k] = ll;
    }
}

// ---------------------------------------------------------------------------
extern "C" void kernel_launch(void* const* d_in, const int* in_sizes, int n_in,
                              void* d_out, int out_size) {
    const float* x     = (const float*)d_in[0];
    const float* mu    = (const float*)d_in[1];
    const float* sigma = (const float*)d_in[2];
    float* out = (float*)d_out;

    chol_inv_kernel<<<NBK, 256>>>(sigma);

    dim3 grid((SEQ + ST - 1) / ST, KST, BATCH);
    ll_kernel<<<grid, 320>>>(x, mu, out);
}

// round 3
// speedup vs baseline: 2.0565x; 1.3843x over previous
#include <cuda_runtime.h>
#include <math.h>

constexpr int NDIM  = 80;
constexpr int BATCH = 64;
constexpr int SEQ   = 1000;
constexpr int KST   = 12;
constexpr int NBK   = BATCH * KST;   // 768
constexpr int ST    = 128;           // samples per block (kernel B)
constexpr int MST   = 82;            // msh row stride (even -> 8B pairs aligned)
constexpr int DST   = 132;           // ds row stride (mult of 4 -> 16B aligned)

constexpr float LOG_2PI = 1.837877066409345339082f;
constexpr float EPS = 1e-5f;

// Per-(b,k) transposed inverse Cholesky factor, dense (zeros where i<j): minvT[j][i] = L^-1[i][j]
__device__ float g_minvT[(size_t)NBK * NDIM * NDIM];
__device__ float g_logdet[NBK];

typedef unsigned long long ull;
__device__ __forceinline__ ull fma2(ull a, ull b, ull c) {
    ull d; asm("fma.rn.f32x2 %0,%1,%2,%3;" : "=l"(d) : "l"(a), "l"(b), "l"(c)); return d;
}
__device__ __forceinline__ ull mul2(ull a, ull b) {
    ull d; asm("mul.rn.f32x2 %0,%1,%2;" : "=l"(d) : "l"(a), "l"(b)); return d;
}
__device__ __forceinline__ ull dup2(float x) {
    ull d; asm("mov.b64 %0,{%1,%1};" : "=l"(d) : "f"(x)); return d;
}
__device__ __forceinline__ float2 asf2(ull v) {
    float2 r; asm("mov.b64 {%0,%1},%2;" : "=f"(r.x), "=f"(r.y) : "l"(v)); return r;
}

// ---------------------------------------------------------------------------
// Kernel A: per (b,k). Division-free LDL elimination (1 sync per k), scale to
// Cholesky L, logdet, then triangular inverse written into the UPPER triangle
// (disjoint from reads -> 1 sync per column). Thread i owns row i.
// ---------------------------------------------------------------------------
__global__ __launch_bounds__(96) void chol_inv_kernel(const float* __restrict__ sigma) {
    __shared__ float A[NDIM][NDIM + 1];   // 25.9 KB
    __shared__ float diagD[NDIM];
    __shared__ float rinv[NDIM];          // 1 / L[k][k]
    __shared__ float lbuf[NDIM];

    const int bk  = blockIdx.x;
    const int tid = threadIdx.x;
    const int i   = tid;                  // row owned (if < NDIM)
    const float* Sg = sigma + (size_t)bk * NDIM * NDIM;

    for (int idx = tid; idx < NDIM * NDIM; idx += 96) {
        int r = idx / NDIM, c = idx % NDIM;   // const divisor -> mul/shift
        float v = Sg[idx];
        if (r == c) v += EPS;
        A[r][c] = v;
    }
    __syncthreads();

    // LDL-style elimination on the lower triangle: A[i][j] -= (A[i][k]/Dk)*A[j][k]
    for (int k = 0; k < NDIM - 1; ++k) {
        if (i > k && i < NDIM) {
            float ci = A[i][k] * (1.0f / A[k][k]);
            for (int j = k + 1; j <= i; ++j)
                A[i][j] -= ci * A[j][k];      // A[j][k]: warp-uniform j -> broadcast
        }
        __syncthreads();
    }

    // Diagonal D, rinv, logdet partials
    if (tid < NDIM) {
        float d = A[tid][tid];
        diagD[tid] = d;
        rinv[tid]  = 1.0f / sqrtf(d);
        lbuf[tid]  = logf(d);
    }
    __syncthreads();
    if (tid == 0) {
        float s = 0.0f;
        for (int j = 0; j < NDIM; ++j) s += lbuf[j];
        g_logdet[bk] = 0.5f * s;
    }
    // Scale to Cholesky: L[i][k] = A[i][k] * rinv[k]  (k < i; diag kept via rinv)
    if (i < NDIM) {
        for (int k = 0; k < i; ++k) A[i][k] *= rinv[k];
    }
    __syncthreads();

    // Triangular inverse X = L^-1, stored into the UPPER triangle: A[j][i] = X[i][j].
    // X[i][j] = -(1/L[j][j]) * ( sum_{k=j+1}^{i-1} X[i][k]*L[k][j] + X[i][i]*L[i][j] )
    for (int jj = NDIM - 1; jj >= 0; --jj) {
        if (i > jj && i < NDIM) {
            float s = rinv[i] * A[i][jj];                 // k = i term
            for (int k = jj + 1; k < i; ++k)
                s = fmaf(A[k][i], A[k][jj], s);           // X[i][k] (upper), L[k][jj] (bcast)
            A[jj][i] = -rinv[jj] * s;
        }
        __syncthreads();
    }

    // Store dense transposed inverse
    float* out = g_minvT + (size_t)bk * NDIM * NDIM;
    for (int idx = tid; idx < NDIM * NDIM; idx += 96) {
        int j = idx / NDIM, c = idx % NDIM;   // out[j][c] = X[c][j]
        float v;
        if (c > j)       v = A[j][c];
        else if (c == j) v = rinv[c];
        else             v = 0.0f;
        out[idx] = v;
    }
}

// ---------------------------------------------------------------------------
// Kernel B: fused z = Minv*diff, quad = |z|^2, ll.
// Block = 160 threads: ty=tid/16 (0..9), tx=tid%16 (0..15).
// Thread: 8 rows {4ty..4ty+3, 76-4ty..79-4ty}, 8 samples (4 f32x2 pairs).
// Work per thread is EXACTLY uniform (164 row-j-steps). Dynamic smem 68.5 KB.
// ---------------------------------------------------------------------------
__global__ __launch_bounds__(160) void ll_kernel(const float* __restrict__ x,
                                                 const float* __restrict__ mu,
                                                 float* __restrict__ out) {
    extern __shared__ float sm[];
    float* msh = sm;                 // [NDIM][MST]  MinvT
    float* ds  = sm + NDIM * MST;    // [NDIM][DST]  diff transposed [n][s]

    const int tid = threadIdx.x;
    const int tx  = tid & 15;
    const int ty  = tid >> 4;        // 0..9
    const int s0  = blockIdx.x * ST;
    const int k   = blockIdx.y;
    const int b   = blockIdx.z;
    const int bk  = b * KST + k;

    // Stage MinvT
    const float* mv = g_minvT + (size_t)bk * NDIM * NDIM;
    for (int idx = tid; idx < NDIM * NDIM; idx += 160) {
        int j = idx / NDIM, i2 = idx % NDIM;
        msh[j * MST + i2] = mv[idx];
    }
    // Stage diff transposed: ds[n][s] = x[b][s0+s][n] - mu[bk][n]
    int navail = SEQ - s0; if (navail > ST) navail = ST;
    const float* xb  = x  + ((size_t)b * SEQ + s0) * NDIM;
    const float* mub = mu + (size_t)bk * NDIM;
    for (int idx = tid; idx < ST * NDIM; idx += 160) {
        int s = idx / NDIM, n = idx % NDIM;
        float v = 0.0f;
        if (s < navail) v = xb[idx] - __ldg(mub + n);
        ds[n * DST + s] = v;
    }
    __syncthreads();

    // acc[r][p]: r = row slot (0..3 = rows 4ty+r "low", 4..7 = rows 76-4ty+r-4 "high"),
    // p = sample pair (samples 8tx+2p, 8tx+2p+1)
    ull acc[8][4];
    #pragma unroll
    for (int r = 0; r < 8; ++r)
        #pragma unroll
        for (int p = 0; p < 4; ++p) acc[r][p] = 0ULL;

    const int rlo = 4 * ty;          // low rows 4ty..4ty+3   (need j <= 4ty+3)
    const int rhi = 76 - 4 * ty;     // high rows 76-4ty..79-4ty (need j <= 79-4ty)
    const int jA  = rlo + 4;         // loop A bound (all 8 rows)
    const int jB  = 80 - rlo;        // loop B bound (high rows only)

    const float* mlo = msh + rlo;
    const float* mhi = msh + rhi;
    const float* dp  = ds + 8 * tx;

    #pragma unroll 2
    for (int j = 0; j < jA; ++j) {
        float2 m01 = *reinterpret_cast<const float2*>(mlo);
        float2 m23 = *reinterpret_cast<const float2*>(mlo + 2);
        float2 m45 = *reinterpret_cast<const float2*>(mhi);
        float2 m67 = *reinterpret_cast<const float2*>(mhi + 2);
        ulonglong2 dA = *reinterpret_cast<const ulonglong2*>(dp);
        ulonglong2 dB = *reinterpret_cast<const ulonglong2*>(dp + 4);
        ull dv0 = dA.x, dv1 = dA.y, dv2 = dB.x, dv3 = dB.y;
        ull m0 = dup2(m01.x), m1 = dup2(m01.y), m2 = dup2(m23.x), m3 = dup2(m23.y);
        ull m4 = dup2(m45.x), m5 = dup2(m45.y), m6 = dup2(m67.x), m7 = dup2(m67.y);
        acc[0][0]=fma2(m0,dv0,acc[0][0]); acc[0][1]=fma2(m0,dv1,acc[0][1]); acc[0][2]=fma2(m0,dv2,acc[0][2]); acc[0][3]=fma2(m0,dv3,acc[0][3]);
        acc[1][0]=fma2(m1,dv0,acc[1][0]); acc[1][1]=fma2(m1,dv1,acc[1][1]); acc[1][2]=fma2(m1,dv2,acc[1][2]); acc[1][3]=fma2(m1,dv3,acc[1][3]);
        acc[2][0]=fma2(m2,dv0,acc[2][0]); acc[2][1]=fma2(m2,dv1,acc[2][1]); acc[2][2]=fma2(m2,dv2,acc[2][2]); acc[2][3]=fma2(m2,dv3,acc[2][3]);
        acc[3][0]=fma2(m3,dv0,acc[3][0]); acc[3][1]=fma2(m3,dv1,acc[3][1]); acc[3][2]=fma2(m3,dv2,acc[3][2]); acc[3][3]=fma2(m3,dv3,acc[3][3]);
        acc[4][0]=fma2(m4,dv0,acc[4][0]); acc[4][1]=fma2(m4,dv1,acc[4][1]); acc[4][2]=fma2(m4,dv2,acc[4][2]); acc[4][3]=fma2(m4,dv3,acc[4][3]);
        acc[5][0]=fma2(m5,dv0,acc[5][0]); acc[5][1]=fma2(m5,dv1,acc[5][1]); acc[5][2]=fma2(m5,dv2,acc[5][2]); acc[5][3]=fma2(m5,dv3,acc[5][3]);
        acc[6][0]=fma2(m6,dv0,acc[6][0]); acc[6][1]=fma2(m6,dv1,acc[6][1]); acc[6][2]=fma2(m6,dv2,acc[6][2]); acc[6][3]=fma2(m6,dv3,acc[6][3]);
        acc[7][0]=fma2(m7,dv0,acc[7][0]); acc[7][1]=fma2(m7,dv1,acc[7][1]); acc[7][2]=fma2(m7,dv2,acc[7][2]); acc[7][3]=fma2(m7,dv3,acc[7][3]);
        mlo += MST; mhi += MST; dp += DST;
    }
    #pragma unroll 2
    for (int j = jA; j < jB; ++j) {
        float2 m45 = *reinterpret_cast<const float2*>(mhi);
        float2 m67 = *reinterpret_cast<const float2*>(mhi + 2);
        ulonglong2 dA = *reinterpret_cast<const ulonglong2*>(dp);
        ulonglong2 dB = *reinterpret_cast<const ulonglong2*>(dp + 4);
        ull dv0 = dA.x, dv1 = dA.y, dv2 = dB.x, dv3 = dB.y;
        ull m4 = dup2(m45.x), m5 = dup2(m45.y), m6 = dup2(m67.x), m7 = dup2(m67.y);
        acc[4][0]=fma2(m4,dv0,acc[4][0]); acc[4][1]=fma2(m4,dv1,acc[4][1]); acc[4][2]=fma2(m4,dv2,acc[4][2]); acc[4][3]=fma2(m4,dv3,acc[4][3]);
        acc[5][0]=fma2(m5,dv0,acc[5][0]); acc[5][1]=fma2(m5,dv1,acc[5][1]); acc[5][2]=fma2(m5,dv2,acc[5][2]); acc[5][3]=fma2(m5,dv3,acc[5][3]);
        acc[6][0]=fma2(m6,dv0,acc[6][0]); acc[6][1]=fma2(m6,dv1,acc[6][1]); acc[6][2]=fma2(m6,dv2,acc[6][2]); acc[6][3]=fma2(m6,dv3,acc[6][3]);
        acc[7][0]=fma2(m7,dv0,acc[7][0]); acc[7][1]=fma2(m7,dv1,acc[7][1]); acc[7][2]=fma2(m7,dv2,acc[7][2]); acc[7][3]=fma2(m7,dv3,acc[7][3]);
        mhi += MST; dp += DST;
    }

    // Per-sample-pair partial quad over this thread's 8 rows
    ull qp[4];
    #pragma unroll
    for (int p = 0; p < 4; ++p) {
        ull q = mul2(acc[0][p], acc[0][p]);
        #pragma unroll
        for (int r = 1; r < 8; ++r) q = fma2(acc[r][p], acc[r][p], q);
        qp[p] = q;
    }

    __syncthreads();   // ds reads done -> reuse as reduction scratch [ty][s]
    {
        float* red = ds + ty * DST + 8 * tx;
        #pragma unroll
        for (int p = 0; p < 4; ++p)
            *reinterpret_cast<ull*>(red + 2 * p) = qp[p];
    }
    __syncthreads();

    if (tid < ST && tid < navail) {
        float sum = 0.0f;
        #pragma unroll
        for (int t = 0; t < 10; ++t) sum += ds[t * DST + tid];
        float ll = -0.5f * sum - g_logdet[bk] - 0.5f * (float)NDIM * LOG_2PI;
        out[((size_t)b * SEQ + s0 + tid) * KST + k] = ll;
    }
}

// ---------------------------------------------------------------------------
extern "C" void kernel_launch(void* const* d_in, const int* in_sizes, int n_in,
                              void* d_out, int out_size) {
    const float* x     = (const float*)d_in[0];
    const float* mu    = (const float*)d_in[1];
    const float* sigma = (const float*)d_in[2];
    float* out = (float*)d_out;

    const int llsmem = (NDIM * MST + NDIM * DST) * sizeof(float);  // 68480 B
    cudaFuncSetAttribute(ll_kernel, cudaFuncAttributeMaxDynamicSharedMemorySize, llsmem);

    chol_inv_kernel<<<NBK, 96>>>(sigma);

    dim3 grid((SEQ + ST - 1) / ST, KST, BATCH);
    ll_kernel<<<grid, 160, llsmem>>>(x, mu, out);
}

// round 4
// speedup vs baseline: 2.1364x; 1.0389x over previous
#include <cuda_runtime.h>
#include <math.h>

constexpr int NDIM  = 80;
constexpr int BATCH = 64;
constexpr int SEQ   = 1000;
constexpr int KST   = 12;
constexpr int NBK   = BATCH * KST;   // 768
constexpr int ST    = 256;           // samples per block (kernel B)
constexpr int MST   = 84;            // msh row stride (mult of 4 -> 16B-aligned quads)
constexpr int DST   = 260;           // ds row stride (mult of 4 -> 16B-aligned)
constexpr int AST   = 82;            // chol A row stride (even -> 8B pairs)

constexpr float LOG_2PI = 1.837877066409345339082f;
constexpr float EPS = 1e-5f;

// Per-(b,k) transposed inverse Cholesky factor, dense (zeros where i<j)
__device__ float g_minvT[(size_t)NBK * NDIM * NDIM];
__device__ float g_logdet[NBK];

typedef unsigned long long ull;
__device__ __forceinline__ ull fma2(ull a, ull b, ull c) {
    ull d; asm("fma.rn.f32x2 %0,%1,%2,%3;" : "=l"(d) : "l"(a), "l"(b), "l"(c)); return d;
}
__device__ __forceinline__ ull mul2(ull a, ull b) {
    ull d; asm("mul.rn.f32x2 %0,%1,%2;" : "=l"(d) : "l"(a), "l"(b)); return d;
}
__device__ __forceinline__ ull dup2(float x) {
    ull d; asm("mov.b64 %0,{%1,%1};" : "=l"(d) : "f"(x)); return d;
}

// ---------------------------------------------------------------------------
// Kernel A: per (b,k). Gauss elimination with pivot-column snapshot (no alias,
// f32x2 pairs), scale to Cholesky L, logdet, triangular inverse into the
// upper triangle. Thread i owns row i.
// ---------------------------------------------------------------------------
__global__ __launch_bounds__(96) void chol_inv_kernel(const float* __restrict__ sigma) {
    __shared__ __align__(16) float A[NDIM * AST];      // 25.6 KB
    __shared__ __align__(16) float colbuf[NDIM + 2];
    __shared__ float rinv[NDIM];
    __shared__ float lbuf[NDIM];
    __shared__ float dinvsh;

    const int bk  = blockIdx.x;
    const int tid = threadIdx.x;
    const int i   = tid;
    const float* Sg = sigma + (size_t)bk * NDIM * NDIM;

    for (int idx = tid; idx < NDIM * NDIM; idx += 96) {
        int r = idx / NDIM, c = idx % NDIM;
        float v = Sg[idx];
        if (r == c) v += EPS;
        A[r * AST + c] = v;
    }
    __syncthreads();

    // Elimination: A[i][j] -= (A[i][k]/A[k][k]) * A[j][k],  j = k+1..i
    for (int k = 0; k < NDIM - 1; ++k) {
        for (int j = tid; j < NDIM; j += 96) colbuf[j] = A[j * AST + k];
        if (tid == 0) dinvsh = 1.0f / A[k * AST + k];
        __syncthreads();
        if (i > k && i < NDIM) {
            float nci = -colbuf[i] * dinvsh;
            float* Ai = A + i * AST;
            int j = k + 1;
            if (j & 1) { Ai[j] = fmaf(nci, colbuf[j], Ai[j]); ++j; }
            ull nci2 = dup2(nci);
            #pragma unroll 4
            for (; j + 1 <= i; j += 2) {
                ull a2 = *reinterpret_cast<ull*>(Ai + j);
                ull c2 = *reinterpret_cast<const ull*>(colbuf + j);
                *reinterpret_cast<ull*>(Ai + j) = fma2(nci2, c2, a2);
            }
            if (j == i) Ai[j] = fmaf(nci, colbuf[j], Ai[j]);
        }
        __syncthreads();
    }

    // Diagonal -> rinv, logdet
    if (tid < NDIM) {
        float d = A[tid * AST + tid];
        rinv[tid] = 1.0f / sqrtf(d);
        lbuf[tid] = logf(d);
    }
    __syncthreads();
    if (tid == 0) {
        float s = 0.0f;
        for (int j = 0; j < NDIM; ++j) s += lbuf[j];
        g_logdet[bk] = 0.5f * s;
    }
    // Scale lower part to Cholesky L: L[i][k] = A[i][k] * rinv[k]  (k < i)
    if (i < NDIM) {
        float* Ai = A + i * AST;
        int k = 0;
        #pragma unroll 4
        for (; k + 1 <= i - 1; k += 2) {
            ull a2 = *reinterpret_cast<ull*>(Ai + k);
            ull r2 = *reinterpret_cast<const ull*>(rinv + k);
            *reinterpret_cast<ull*>(Ai + k) = mul2(a2, r2);
        }
        if (k <= i - 1) Ai[k] *= rinv[k];
    }
    __syncthreads();

    // Triangular inverse X = L^-1 into the UPPER triangle: A[jj][i] = X[i][jj]
    // X[i][jj] = -rinv[jj] * ( rinv[i]*L[i][jj] + sum_{k=jj+1}^{i-1} X[i][k]*L[k][jj] )
    for (int jj = NDIM - 2; jj >= 0; --jj) {
        if (i > jj && i < NDIM) {
            float s = rinv[i] * A[i * AST + jj];
            #pragma unroll 4
            for (int k = jj + 1; k < i; ++k)
                s = fmaf(A[k * AST + i], A[k * AST + jj], s);
            A[jj * AST + i] = -rinv[jj] * s;
        }
        __syncthreads();
    }

    // Store dense transposed inverse: out[j][c] = X[c][j]
    float* out = g_minvT + (size_t)bk * NDIM * NDIM;
    for (int idx = tid; idx < NDIM * NDIM; idx += 96) {
        int j = idx / NDIM, c = idx % NDIM;
        float v;
        if (c > j)       v = A[j * AST + c];
        else if (c == j) v = rinv[c];
        else             v = 0.0f;
        out[idx] = v;
    }
}

// ---------------------------------------------------------------------------
// Kernel B: fused z = Minv*diff, quad = |z|^2, ll.
// 320 threads: warp w = ty (0..9), lanes tx (0..31). Thread: 8 rows
// {4ty..4ty+3, 76-4ty..79-4ty} (uniform 164 j-steps), 8 samples (f32x2 pairs).
// m loads are warp-uniform LDS.128 broadcasts. smem 107.5 KB -> 2 blocks/SM.
// ---------------------------------------------------------------------------
__global__ __launch_bounds__(320, 2) void ll_kernel(const float* __restrict__ x,
                                                    const float* __restrict__ mu,
                                                    float* __restrict__ out) {
    extern __shared__ float sm[];
    float* msh = sm;                 // [NDIM][MST]  MinvT
    float* ds  = sm + NDIM * MST;    // [NDIM][DST]  diff transposed [n][s]

    const int tid = threadIdx.x;
    const int tx  = tid & 31;
    const int ty  = tid >> 5;        // 0..9 (= warp id)
    const int s0  = blockIdx.x * ST;
    const int k   = blockIdx.y;
    const int b   = blockIdx.z;
    const int bk  = b * KST + k;

    // Stage MinvT
    const float* mv = g_minvT + (size_t)bk * NDIM * NDIM;
    for (int idx = tid; idx < NDIM * NDIM; idx += 320) {
        int j = idx / NDIM, i2 = idx % NDIM;
        msh[j * MST + i2] = mv[idx];
    }
    // Stage diff transposed: ds[n][s] = x[b][s0+s][n] - mu[bk][n]
    int navail = SEQ - s0; if (navail > ST) navail = ST;
    const float* xb  = x  + ((size_t)b * SEQ + s0) * NDIM;
    const float* mub = mu + (size_t)bk * NDIM;
    for (int idx = tid; idx < ST * NDIM; idx += 320) {
        int s = idx / NDIM, n = idx % NDIM;
        float v = 0.0f;
        if (s < navail) v = xb[idx] - __ldg(mub + n);
        ds[n * DST + s] = v;
    }
    __syncthreads();

    // acc[r][p]: r = row slot (0..3 low rows 4ty+r, 4..7 high rows 76-4ty+(r-4)),
    // p = sample pair (samples 8tx+2p, 8tx+2p+1)
    ull acc[8][4];
    #pragma unroll
    for (int r = 0; r < 8; ++r)
        #pragma unroll
        for (int p = 0; p < 4; ++p) acc[r][p] = 0ULL;

    const int rlo = 4 * ty;
    const int rhi = 76 - 4 * ty;
    const int jA  = rlo + 4;
    const int jB  = 80 - rlo;

    const float* mlo = msh + rlo;
    const float* mhi = msh + rhi;
    const float* dp  = ds + 8 * tx;

    #pragma unroll 2
    for (int j = 0; j < jA; ++j) {
        float4 ml = *reinterpret_cast<const float4*>(mlo);   // rows rlo..rlo+3
        float4 mh = *reinterpret_cast<const float4*>(mhi);   // rows rhi..rhi+3
        ulonglong2 dA = *reinterpret_cast<const ulonglong2*>(dp);
        ulonglong2 dB = *reinterpret_cast<const ulonglong2*>(dp + 4);
        ull dv0 = dA.x, dv1 = dA.y, dv2 = dB.x, dv3 = dB.y;
        ull m;
        m = dup2(ml.x); acc[0][0]=fma2(m,dv0,acc[0][0]); acc[0][1]=fma2(m,dv1,acc[0][1]); acc[0][2]=fma2(m,dv2,acc[0][2]); acc[0][3]=fma2(m,dv3,acc[0][3]);
        m = dup2(ml.y); acc[1][0]=fma2(m,dv0,acc[1][0]); acc[1][1]=fma2(m,dv1,acc[1][1]); acc[1][2]=fma2(m,dv2,acc[1][2]); acc[1][3]=fma2(m,dv3,acc[1][3]);
        m = dup2(ml.z); acc[2][0]=fma2(m,dv0,acc[2][0]); acc[2][1]=fma2(m,dv1,acc[2][1]); acc[2][2]=fma2(m,dv2,acc[2][2]); acc[2][3]=fma2(m,dv3,acc[2][3]);
        m = dup2(ml.w); acc[3][0]=fma2(m,dv0,acc[3][0]); acc[3][1]=fma2(m,dv1,acc[3][1]); acc[3][2]=fma2(m,dv2,acc[3][2]); acc[3][3]=fma2(m,dv3,acc[3][3]);
        m = dup2(mh.x); acc[4][0]=fma2(m,dv0,acc[4][0]); acc[4][1]=fma2(m,dv1,acc[4][1]); acc[4][2]=fma2(m,dv2,acc[4][2]); acc[4][3]=fma2(m,dv3,acc[4][3]);
        m = dup2(mh.y); acc[5][0]=fma2(m,dv0,acc[5][0]); acc[5][1]=fma2(m,dv1,acc[5][1]); acc[5][2]=fma2(m,dv2,acc[5][2]); acc[5][3]=fma2(m,dv3,acc[5][3]);
        m = dup2(mh.z); acc[6][0]=fma2(m,dv0,acc[6][0]); acc[6][1]=fma2(m,dv1,acc[6][1]); acc[6][2]=fma2(m,dv2,acc[6][2]); acc[6][3]=fma2(m,dv3,acc[6][3]);
        m = dup2(mh.w); acc[7][0]=fma2(m,dv0,acc[7][0]); acc[7][1]=fma2(m,dv1,acc[7][1]); acc[7][2]=fma2(m,dv2,acc[7][2]); acc[7][3]=fma2(m,dv3,acc[7][3]);
        mlo += MST; mhi += MST; dp += DST;
    }
    #pragma unroll 2
    for (int j = jA; j < jB; ++j) {
        float4 mh = *reinterpret_cast<const float4*>(mhi);
        ulonglong2 dA = *reinterpret_cast<const ulonglong2*>(dp);
        ulonglong2 dB = *reinterpret_cast<const ulonglong2*>(dp + 4);
        ull dv0 = dA.x, dv1 = dA.y, dv2 = dB.x, dv3 = dB.y;
        ull m;
        m = dup2(mh.x); acc[4][0]=fma2(m,dv0,acc[4][0]); acc[4][1]=fma2(m,dv1,acc[4][1]); acc[4][2]=fma2(m,dv2,acc[4][2]); acc[4][3]=fma2(m,dv3,acc[4][3]);
        m = dup2(mh.y); acc[5][0]=fma2(m,dv0,acc[5][0]); acc[5][1]=fma2(m,dv1,acc[5][1]); acc[5][2]=fma2(m,dv2,acc[5][2]); acc[5][3]=fma2(m,dv3,acc[5][3]);
        m = dup2(mh.z); acc[6][0]=fma2(m,dv0,acc[6][0]); acc[6][1]=fma2(m,dv1,acc[6][1]); acc[6][2]=fma2(m,dv2,acc[6][2]); acc[6][3]=fma2(m,dv3,acc[6][3]);
        m = dup2(mh.w); acc[7][0]=fma2(m,dv0,acc[7][0]); acc[7][1]=fma2(m,dv1,acc[7][1]); acc[7][2]=fma2(m,dv2,acc[7][2]); acc[7][3]=fma2(m,dv3,acc[7][3]);
        mhi += MST; dp += DST;
    }

    // Per-sample-pair partial quad over this thread's 8 rows
    ull qp[4];
    #pragma unroll
    for (int p = 0; p < 4; ++p) {
        ull q = mul2(acc[0][p], acc[0][p]);
        #pragma unroll
        for (int r = 1; r < 8; ++r) q = fma2(acc[r][p], acc[r][p], q);
        qp[p] = q;
    }

    __syncthreads();   // ds reads done -> reuse as reduction scratch [ty][s]
    {
        float* red = ds + ty * DST + 8 * tx;
        #pragma unroll
        for (int p = 0; p < 4; ++p)
            *reinterpret_cast<ull*>(red + 2 * p) = qp[p];
    }
    __syncthreads();

    if (tid < ST && tid < navail) {
        float sum = 0.0f;
        #pragma unroll
        for (int t = 0; t < 10; ++t) sum += ds[t * DST + tid];
        float ll = -0.5f * sum - g_logdet[bk] - 0.5f * (float)NDIM * LOG_2PI;
        out[((size_t)b * SEQ + s0 + tid) * KST + k] = ll;
    }
}

// ---------------------------------------------------------------------------
extern "C" void kernel_launch(void* const* d_in, const int* in_sizes, int n_in,
                              void* d_out, int out_size) {
    const float* x     = (const float*)d_in[0];
    const float* mu    = (const float*)d_in[1];
    const float* sigma = (const float*)d_in[2];
    float* out = (float*)d_out;

    const int llsmem = (NDIM * MST + NDIM * DST) * sizeof(float);  // 110080 B
    cudaFuncSetAttribute(ll_kernel, cudaFuncAttributeMaxDynamicSharedMemorySize, llsmem);

    chol_inv_kernel<<<NBK, 96>>>(sigma);

    dim3 grid((SEQ + ST - 1) / ST, KST, BATCH);
    ll_kernel<<<grid, 320, llsmem>>>(x, mu, out);
}

// round 5
// speedup vs baseline: 2.4929x; 1.1669x over previous
#include <cuda_runtime.h>
#include <math.h>

constexpr int NDIM  = 80;
constexpr int BATCH = 64;
constexpr int SEQ   = 1000;
constexpr int KST   = 12;
constexpr int NBK   = BATCH * KST;   // 768
constexpr int ST    = 256;           // samples per block (kernel B)
constexpr int SH    = 128;           // half-tile
constexpr int MST   = 84;            // msh row stride (mult of 4 -> 16B-aligned quads)
constexpr int DST   = 260;           // ds row stride (mult of 4 -> 16B-aligned)
constexpr int AST   = 82;            // chol A row stride

constexpr float LOG_2PI = 1.837877066409345339082f;
constexpr float EPS = 1e-5f;

__device__ float g_minvT[(size_t)NBK * NDIM * NDIM];
__device__ float g_logdet[NBK];

typedef unsigned long long ull;
__device__ __forceinline__ ull fma2(ull a, ull b, ull c) {
    ull d; asm("fma.rn.f32x2 %0,%1,%2,%3;" : "=l"(d) : "l"(a), "l"(b), "l"(c)); return d;
}
__device__ __forceinline__ ull mul2(ull a, ull b) {
    ull d; asm("mul.rn.f32x2 %0,%1,%2;" : "=l"(d) : "l"(a), "l"(b)); return d;
}
__device__ __forceinline__ ull dup2(float x) {
    ull d; asm("mov.b64 %0,{%1,%1};" : "=l"(d) : "f"(x)); return d;
}

// ---------------------------------------------------------------------------
// Kernel A: per (b,k). Gauss elimination (pivot-column snapshot, f32x2),
// scale to Cholesky L, logdet, then SYNC-FREE triangular inverse into the
// upper triangle (column i is private to thread i). Thread i owns row i.
// ---------------------------------------------------------------------------
__global__ __launch_bounds__(96) void chol_inv_kernel(const float* __restrict__ sigma) {
    __shared__ __align__(16) float A[NDIM * AST];      // 25.6 KB
    __shared__ __align__(16) float colbuf[NDIM + 2];
    __shared__ float rinv[NDIM];
    __shared__ float lbuf[NDIM];
    __shared__ float dinvsh;

    const int bk  = blockIdx.x;
    const int tid = threadIdx.x;
    const int i   = tid;
    const float* Sg = sigma + (size_t)bk * NDIM * NDIM;

    for (int idx = tid; idx < NDIM * NDIM; idx += 96) {
        int r = idx / NDIM, c = idx % NDIM;
        float v = Sg[idx];
        if (r == c) v += EPS;
        A[r * AST + c] = v;
    }
    __syncthreads();

    // Elimination on the lower triangle
    for (int k = 0; k < NDIM - 1; ++k) {
        for (int j = tid; j < NDIM; j += 96) colbuf[j] = A[j * AST + k];
        if (tid == 0) dinvsh = 1.0f / A[k * AST + k];
        __syncthreads();
        if (i > k && i < NDIM) {
            float nci = -colbuf[i] * dinvsh;
            float* Ai = A + i * AST;
            int j = k + 1;
            if (j & 1) { Ai[j] = fmaf(nci, colbuf[j], Ai[j]); ++j; }
            ull nci2 = dup2(nci);
            #pragma unroll 4
            for (; j + 1 <= i; j += 2) {
                ull a2 = *reinterpret_cast<ull*>(Ai + j);
                ull c2 = *reinterpret_cast<const ull*>(colbuf + j);
                *reinterpret_cast<ull*>(Ai + j) = fma2(nci2, c2, a2);
            }
            if (j == i) Ai[j] = fmaf(nci, colbuf[j], Ai[j]);
        }
        __syncthreads();
    }

    if (tid < NDIM) {
        float d = A[tid * AST + tid];
        rinv[tid] = 1.0f / sqrtf(d);
        lbuf[tid] = logf(d);
    }
    __syncthreads();
    if (tid == 0) {
        float s = 0.0f;
        for (int j = 0; j < NDIM; ++j) s += lbuf[j];
        g_logdet[bk] = 0.5f * s;
    }
    // Scale lower part to Cholesky L: L[i][k] = A[i][k] * rinv[k]  (k < i)
    if (i < NDIM) {
        float* Ai = A + i * AST;
        int k = 0;
        #pragma unroll 4
        for (; k + 1 <= i - 1; k += 2) {
            ull a2 = *reinterpret_cast<ull*>(Ai + k);
            ull r2 = *reinterpret_cast<const ull*>(rinv + k);
            *reinterpret_cast<ull*>(Ai + k) = mul2(a2, r2);
        }
        if (k <= i - 1) Ai[k] *= rinv[k];
    }
    __syncthreads();

    // Sync-free triangular inverse X = L^-1 into the UPPER triangle.
    // Column i of the upper triangle is written only by thread i; thread i
    // reads only its own prior writes (A[k][i], k>jj) and the stable L.
    if (i > 0 && i < NDIM) {
        for (int jj = i - 1; jj >= 0; --jj) {
            float s = rinv[i] * A[i * AST + jj];
            #pragma unroll 4
            for (int k = jj + 1; k < i; ++k)
                s = fmaf(A[k * AST + i], A[k * AST + jj], s);
            A[jj * AST + i] = -rinv[jj] * s;
        }
    }
    __syncthreads();

    // Store dense transposed inverse: out[j][c] = X[c][j]
    float* out = g_minvT + (size_t)bk * NDIM * NDIM;
    for (int idx = tid; idx < NDIM * NDIM; idx += 96) {
        int j = idx / NDIM, c = idx % NDIM;
        float v;
        if (c > j)       v = A[j * AST + c];
        else if (c == j) v = rinv[c];
        else             v = 0.0f;
        out[idx] = v;
    }
}

// ---------------------------------------------------------------------------
// Kernel B: fused z = Minv*diff, quad = |z|^2, ll.
// 320 threads: ty = warp (0..9), tx = lane (0..31). Thread: 8 rows
// {4ty..4ty+3, 76-4ty..79-4ty} (uniform 164 j-steps), 8 samples
// {4tx..4tx+3} U {128+4tx..128+4tx+3} -> dense conflict-free LDS.128 d-loads.
// smem 110 KB -> 2 blocks/SM.
// ---------------------------------------------------------------------------
__global__ __launch_bounds__(320, 2) void ll_kernel(const float* __restrict__ x,
                                                    const float* __restrict__ mu,
                                                    float* __restrict__ out) {
    extern __shared__ float sm[];
    float* msh = sm;                 // [NDIM][MST]
    float* ds  = sm + NDIM * MST;    // [NDIM][DST]

    const int tid = threadIdx.x;
    const int tx  = tid & 31;
    const int ty  = tid >> 5;        // warp id 0..9
    const int s0  = blockIdx.x * ST;
    const int k   = blockIdx.y;
    const int b   = blockIdx.z;
    const int bk  = b * KST + k;

    const float* mv = g_minvT + (size_t)bk * NDIM * NDIM;
    for (int idx = tid; idx < NDIM * NDIM; idx += 320) {
        int j = idx / NDIM, i2 = idx % NDIM;
        msh[j * MST + i2] = mv[idx];
    }
    int navail = SEQ - s0; if (navail > ST) navail = ST;
    const float* xb  = x  + ((size_t)b * SEQ + s0) * NDIM;
    const float* mub = mu + (size_t)bk * NDIM;
    for (int idx = tid; idx < ST * NDIM; idx += 320) {
        int s = idx / NDIM, n = idx % NDIM;
        float v = 0.0f;
        if (s < navail) v = xb[idx] - __ldg(mub + n);
        ds[n * DST + s] = v;
    }
    __syncthreads();

    // acc[r][p]: r = row slot (0..3 low, 4..7 high); p = sample pair:
    // p=0,1 -> samples 4tx..4tx+3 ; p=2,3 -> samples 128+4tx..128+4tx+3
    ull acc[8][4];
    #pragma unroll
    for (int r = 0; r < 8; ++r)
        #pragma unroll
        for (int p = 0; p < 4; ++p) acc[r][p] = 0ULL;

    const int rlo = 4 * ty;
    const int rhi = 76 - 4 * ty;
    const int jA  = rlo + 4;
    const int jB  = 80 - rlo;

    const float* mlo = msh + rlo;
    const float* mhi = msh + rhi;
    const float* dp0 = ds + 4 * tx;        // dense: lane stride 16B
    const float* dp1 = ds + SH + 4 * tx;   // dense: lane stride 16B

    #pragma unroll 2
    for (int j = 0; j < jA; ++j) {
        float4 ml = *reinterpret_cast<const float4*>(mlo);
        float4 mh = *reinterpret_cast<const float4*>(mhi);
        ulonglong2 dA = *reinterpret_cast<const ulonglong2*>(dp0);
        ulonglong2 dB = *reinterpret_cast<const ulonglong2*>(dp1);
        ull dv0 = dA.x, dv1 = dA.y, dv2 = dB.x, dv3 = dB.y;
        ull m;
        m = dup2(ml.x); acc[0][0]=fma2(m,dv0,acc[0][0]); acc[0][1]=fma2(m,dv1,acc[0][1]); acc[0][2]=fma2(m,dv2,acc[0][2]); acc[0][3]=fma2(m,dv3,acc[0][3]);
        m = dup2(ml.y); acc[1][0]=fma2(m,dv0,acc[1][0]); acc[1][1]=fma2(m,dv1,acc[1][1]); acc[1][2]=fma2(m,dv2,acc[1][2]); acc[1][3]=fma2(m,dv3,acc[1][3]);
        m = dup2(ml.z); acc[2][0]=fma2(m,dv0,acc[2][0]); acc[2][1]=fma2(m,dv1,acc[2][1]); acc[2][2]=fma2(m,dv2,acc[2][2]); acc[2][3]=fma2(m,dv3,acc[2][3]);
        m = dup2(ml.w); acc[3][0]=fma2(m,dv0,acc[3][0]); acc[3][1]=fma2(m,dv1,acc[3][1]); acc[3][2]=fma2(m,dv2,acc[3][2]); acc[3][3]=fma2(m,dv3,acc[3][3]);
        m = dup2(mh.x); acc[4][0]=fma2(m,dv0,acc[4][0]); acc[4][1]=fma2(m,dv1,acc[4][1]); acc[4][2]=fma2(m,dv2,acc[4][2]); acc[4][3]=fma2(m,dv3,acc[4][3]);
        m = dup2(mh.y); acc[5][0]=fma2(m,dv0,acc[5][0]); acc[5][1]=fma2(m,dv1,acc[5][1]); acc[5][2]=fma2(m,dv2,acc[5][2]); acc[5][3]=fma2(m,dv3,acc[5][3]);
        m = dup2(mh.z); acc[6][0]=fma2(m,dv0,acc[6][0]); acc[6][1]=fma2(m,dv1,acc[6][1]); acc[6][2]=fma2(m,dv2,acc[6][2]); acc[6][3]=fma2(m,dv3,acc[6][3]);
        m = dup2(mh.w); acc[7][0]=fma2(m,dv0,acc[7][0]); acc[7][1]=fma2(m,dv1,acc[7][1]); acc[7][2]=fma2(m,dv2,acc[7][2]); acc[7][3]=fma2(m,dv3,acc[7][3]);
        mlo += MST; mhi += MST; dp0 += DST; dp1 += DST;
    }
    #pragma unroll 2
    for (int j = jA; j < jB; ++j) {
        float4 mh = *reinterpret_cast<const float4*>(mhi);
        ulonglong2 dA = *reinterpret_cast<const ulonglong2*>(dp0);
        ulonglong2 dB = *reinterpret_cast<const ulonglong2*>(dp1);
        ull dv0 = dA.x, dv1 = dA.y, dv2 = dB.x, dv3 = dB.y;
        ull m;
        m = dup2(mh.x); acc[4][0]=fma2(m,dv0,acc[4][0]); acc[4][1]=fma2(m,dv1,acc[4][1]); acc[4][2]=fma2(m,dv2,acc[4][2]); acc[4][3]=fma2(m,dv3,acc[4][3]);
        m = dup2(mh.y); acc[5][0]=fma2(m,dv0,acc[5][0]); acc[5][1]=fma2(m,dv1,acc[5][1]); acc[5][2]=fma2(m,dv2,acc[5][2]); acc[5][3]=fma2(m,dv3,acc[5][3]);
        m = dup2(mh.z); acc[6][0]=fma2(m,dv0,acc[6][0]); acc[6][1]=fma2(m,dv1,acc[6][1]); acc[6][2]=fma2(m,dv2,acc[6][2]); acc[6][3]=fma2(m,dv3,acc[6][3]);
        m = dup2(mh.w); acc[7][0]=fma2(m,dv0,acc[7][0]); acc[7][1]=fma2(m,dv1,acc[7][1]); acc[7][2]=fma2(m,dv2,acc[7][2]); acc[7][3]=fma2(m,dv3,acc[7][3]);
        mhi += MST; dp0 += DST; dp1 += DST;
    }

    // Partial quad per sample pair over this thread's 8 rows
    ull qp[4];
    #pragma unroll
    for (int p = 0; p < 4; ++p) {
        ull q = mul2(acc[0][p], acc[0][p]);
        #pragma unroll
        for (int r = 1; r < 8; ++r) q = fma2(acc[r][p], acc[r][p], q);
        qp[p] = q;
    }

    __syncthreads();   // ds reads done -> reuse as scratch [ty][s]
    {
        float* red = ds + ty * DST;
        *reinterpret_cast<ull*>(red + 4 * tx)          = qp[0];
        *reinterpret_cast<ull*>(red + 4 * tx + 2)      = qp[1];
        *reinterpret_cast<ull*>(red + SH + 4 * tx)     = qp[2];
        *reinterpret_cast<ull*>(red + SH + 4 * tx + 2) = qp[3];
    }
    __syncthreads();

    if (tid < ST && tid < navail) {
        float sum = 0.0f;
        #pragma unroll
        for (int t = 0; t < 10; ++t) sum += ds[t * DST + tid];
        float ll = -0.5f * sum - g_logdet[bk] - 0.5f * (float)NDIM * LOG_2PI;
        out[((size_t)b * SEQ + s0 + tid) * KST + k] = ll;
    }
}

// ---------------------------------------------------------------------------
extern "C" void kernel_launch(void* const* d_in, const int* in_sizes, int n_in,
                              void* d_out, int out_size) {
    const float* x     = (const float*)d_in[0];
    const float* mu    = (const float*)d_in[1];
    const float* sigma = (const float*)d_in[2];
    float* out = (float*)d_out;

    const int llsmem = (NDIM * MST + NDIM * DST) * sizeof(float);  // 110080 B
    cudaFuncSetAttribute(ll_kernel, cudaFuncAttributeMaxDynamicSharedMemorySize, llsmem);

    chol_inv_kernel<<<NBK, 96>>>(sigma);

    dim3 grid((SEQ + ST - 1) / ST, KST, BATCH);
    ll_kernel<<<grid, 320, llsmem>>>(x, mu, out);
}

// round 6
// speedup vs baseline: 2.5775x; 1.0339x over previous
#include <cuda_runtime.h>
#include <math.h>

constexpr int NDIM  = 80;
constexpr int BATCH = 64;
constexpr int SEQ   = 1000;
constexpr int KST   = 12;
constexpr int NBK   = BATCH * KST;   // 768
constexpr int ST    = 128;           // samples per block (kernel B)
constexpr int MST   = 84;            // msh row stride (mult of 4 -> 16B aligned)
constexpr int DST   = 132;           // ds row stride (mult of 4 -> 16B aligned)
constexpr int AST   = 82;            // chol A row stride

constexpr float LOG_2PI = 1.837877066409345339082f;
constexpr float EPS = 1e-5f;

__device__ float g_minvT[(size_t)NBK * NDIM * NDIM];
__device__ float g_logdet[NBK];

typedef unsigned long long ull;
__device__ __forceinline__ ull fma2(ull a, ull b, ull c) {
    ull d; asm("fma.rn.f32x2 %0,%1,%2,%3;" : "=l"(d) : "l"(a), "l"(b), "l"(c)); return d;
}
__device__ __forceinline__ ull mul2(ull a, ull b) {
    ull d; asm("mul.rn.f32x2 %0,%1,%2;" : "=l"(d) : "l"(a), "l"(b)); return d;
}
__device__ __forceinline__ ull dup2(float x) {
    ull d; asm("mov.b64 %0,{%1,%1};" : "=l"(d) : "f"(x)); return d;
}
__device__ __forceinline__ float2 asf2(ull v) {
    float2 r; asm("mov.b64 {%0,%1},%2;" : "=f"(r.x), "=f"(r.y) : "l"(v)); return r;
}

// ---------------------------------------------------------------------------
// Kernel A: per (b,k). Gauss elimination (pivot-column snapshot, f32x2),
// scale to Cholesky L, logdet, sync-free triangular inverse into the upper
// triangle (column i private to thread i; 4-way ILP on the reduction).
// ---------------------------------------------------------------------------
__global__ __launch_bounds__(96) void chol_inv_kernel(const float* __restrict__ sigma) {
    __shared__ __align__(16) float A[NDIM * AST];      // 25.6 KB
    __shared__ __align__(16) float colbuf[NDIM + 2];
    __shared__ float rinv[NDIM];
    __shared__ float lbuf[NDIM];
    __shared__ float dinvsh;

    const int bk  = blockIdx.x;
    const int tid = threadIdx.x;
    const int i   = tid;
    const float* Sg = sigma + (size_t)bk * NDIM * NDIM;

    for (int idx = tid; idx < NDIM * NDIM; idx += 96) {
        int r = idx / NDIM, c = idx % NDIM;
        float v = Sg[idx];
        if (r == c) v += EPS;
        A[r * AST + c] = v;
    }
    __syncthreads();

    for (int k = 0; k < NDIM - 1; ++k) {
        for (int j = tid; j < NDIM; j += 96) colbuf[j] = A[j * AST + k];
        if (tid == 0) dinvsh = 1.0f / A[k * AST + k];
        __syncthreads();
        if (i > k && i < NDIM) {
            float nci = -colbuf[i] * dinvsh;
            float* Ai = A + i * AST;
            int j = k + 1;
            if (j & 1) { Ai[j] = fmaf(nci, colbuf[j], Ai[j]); ++j; }
            ull nci2 = dup2(nci);
            #pragma unroll 4
            for (; j + 1 <= i; j += 2) {
                ull a2 = *reinterpret_cast<ull*>(Ai + j);
                ull c2 = *reinterpret_cast<const ull*>(colbuf + j);
                *reinterpret_cast<ull*>(Ai + j) = fma2(nci2, c2, a2);
            }
            if (j == i) Ai[j] = fmaf(nci, colbuf[j], Ai[j]);
        }
        __syncthreads();
    }

    if (tid < NDIM) {
        float d = A[tid * AST + tid];
        rinv[tid] = 1.0f / sqrtf(d);
        lbuf[tid] = logf(d);
    }
    __syncthreads();
    if (tid == 0) {
        float s = 0.0f;
        for (int j = 0; j < NDIM; ++j) s += lbuf[j];
        g_logdet[bk] = 0.5f * s;
    }
    // Scale lower part to Cholesky L
    if (i < NDIM) {
        float* Ai = A + i * AST;
        int k = 0;
        #pragma unroll 4
        for (; k + 1 <= i - 1; k += 2) {
            ull a2 = *reinterpret_cast<ull*>(Ai + k);
            ull r2 = *reinterpret_cast<const ull*>(rinv + k);
            *reinterpret_cast<ull*>(Ai + k) = mul2(a2, r2);
        }
        if (k <= i - 1) Ai[k] *= rinv[k];
    }
    __syncthreads();

    // Sync-free triangular inverse X = L^-1 into the UPPER triangle.
    if (i > 0 && i < NDIM) {
        for (int jj = i - 1; jj >= 0; --jj) {
            float s0 = rinv[i] * A[i * AST + jj];
            float s1 = 0.f, s2 = 0.f, s3 = 0.f;
            int k = jj + 1;
            for (; k + 3 < i; k += 4) {
                s0 = fmaf(A[k * AST + i],       A[k * AST + jj],       s0);
                s1 = fmaf(A[(k+1) * AST + i],   A[(k+1) * AST + jj],   s1);
                s2 = fmaf(A[(k+2) * AST + i],   A[(k+2) * AST + jj],   s2);
                s3 = fmaf(A[(k+3) * AST + i],   A[(k+3) * AST + jj],   s3);
            }
            for (; k < i; ++k)
                s0 = fmaf(A[k * AST + i], A[k * AST + jj], s0);
            A[jj * AST + i] = -rinv[jj] * ((s0 + s1) + (s2 + s3));
        }
    }
    __syncthreads();

    float* out = g_minvT + (size_t)bk * NDIM * NDIM;
    for (int idx = tid; idx < NDIM * NDIM; idx += 96) {
        int j = idx / NDIM, c = idx % NDIM;
        float v;
        if (c > j)       v = A[j * AST + c];
        else if (c == j) v = rinv[c];
        else             v = 0.0f;
        out[idx] = v;
    }
}

// ---------------------------------------------------------------------------
// Kernel B: fused z = Minv*diff, quad = |z|^2, ll.
// 320 threads, 3 blocks/SM (smem 69.1 KB). ty = warp (0..9), tx = lane.
// Thread: 8 rows {4ty..4ty+3, 76-4ty..79-4ty} (uniform work), 4 samples
// {4tx..4tx+3}. ROW-PAIRED f32x2 accumulators: m row-pairs load directly as
// ull (no dup MOVs); only 4 dup2 per j for the samples.
// ---------------------------------------------------------------------------
__global__ __launch_bounds__(320, 3) void ll_kernel(const float* __restrict__ x,
                                                    const float* __restrict__ mu,
                                                    float* __restrict__ out) {
    extern __shared__ float sm[];
    float* msh = sm;                 // [NDIM][MST]
    float* ds  = sm + NDIM * MST;    // [NDIM][DST]

    const int tid = threadIdx.x;
    const int tx  = tid & 31;
    const int ty  = tid >> 5;        // warp id 0..9
    const int s0  = blockIdx.x * ST;
    const int k   = blockIdx.y;
    const int b   = blockIdx.z;
    const int bk  = b * KST + k;

    const float* mv = g_minvT + (size_t)bk * NDIM * NDIM;
    for (int idx = tid; idx < NDIM * NDIM; idx += 320) {
        int j = idx / NDIM, i2 = idx % NDIM;
        msh[j * MST + i2] = mv[idx];
    }
    int navail = SEQ - s0; if (navail > ST) navail = ST;
    const float* xb  = x  + ((size_t)b * SEQ + s0) * NDIM;
    const float* mub = mu + (size_t)bk * NDIM;
    for (int idx = tid; idx < ST * NDIM; idx += 320) {
        int s = idx / NDIM, n = idx % NDIM;
        float v = 0.0f;
        if (s < navail) v = xb[idx] - __ldg(mub + n);
        ds[n * DST + s] = v;
    }
    __syncthreads();

    // acc[p][s]: p = row pair (0: rows rlo,rlo+1; 1: rlo+2,rlo+3;
    //                          2: rhi,rhi+1; 3: rhi+2,rhi+3), s = sample 0..3
    ull acc[4][4];
    #pragma unroll
    for (int p = 0; p < 4; ++p)
        #pragma unroll
        for (int s = 0; s < 4; ++s) acc[p][s] = 0ULL;

    const int rlo = 4 * ty;
    const int rhi = 76 - 4 * ty;
    const int jA  = rlo + 4;        // all 8 rows active
    const int jB  = 80 - rlo;       // high rows only

    const float* mlo = msh + rlo;
    const float* mhi = msh + rhi;
    const float* dp  = ds + 4 * tx;  // lane stride 16B -> conflict-free LDS.128

    #pragma unroll 2
    for (int j = 0; j < jA; ++j) {
        ulonglong2 mlp = *reinterpret_cast<const ulonglong2*>(mlo);  // {m[rlo],m[rlo+1]},{m[rlo+2],m[rlo+3]}
        ulonglong2 mhp = *reinterpret_cast<const ulonglong2*>(mhi);
        float4 d4 = *reinterpret_cast<const float4*>(dp);
        ull d0 = dup2(d4.x), d1 = dup2(d4.y), d2 = dup2(d4.z), d3 = dup2(d4.w);
        acc[0][0]=fma2(mlp.x,d0,acc[0][0]); acc[0][1]=fma2(mlp.x,d1,acc[0][1]); acc[0][2]=fma2(mlp.x,d2,acc[0][2]); acc[0][3]=fma2(mlp.x,d3,acc[0][3]);
        acc[1][0]=fma2(mlp.y,d0,acc[1][0]); acc[1][1]=fma2(mlp.y,d1,acc[1][1]); acc[1][2]=fma2(mlp.y,d2,acc[1][2]); acc[1][3]=fma2(mlp.y,d3,acc[1][3]);
        acc[2][0]=fma2(mhp.x,d0,acc[2][0]); acc[2][1]=fma2(mhp.x,d1,acc[2][1]); acc[2][2]=fma2(mhp.x,d2,acc[2][2]); acc[2][3]=fma2(mhp.x,d3,acc[2][3]);
        acc[3][0]=fma2(mhp.y,d0,acc[3][0]); acc[3][1]=fma2(mhp.y,d1,acc[3][1]); acc[3][2]=fma2(mhp.y,d2,acc[3][2]); acc[3][3]=fma2(mhp.y,d3,acc[3][3]);
        mlo += MST; mhi += MST; dp += DST;
    }
    #pragma unroll 2
    for (int j = jA; j < jB; ++j) {
        ulonglong2 mhp = *reinterpret_cast<const ulonglong2*>(mhi);
        float4 d4 = *reinterpret_cast<const float4*>(dp);
        ull d0 = dup2(d4.x), d1 = dup2(d4.y), d2 = dup2(d4.z), d3 = dup2(d4.w);
        acc[2][0]=fma2(mhp.x,d0,acc[2][0]); acc[2][1]=fma2(mhp.x,d1,acc[2][1]); acc[2][2]=fma2(mhp.x,d2,acc[2][2]); acc[2][3]=fma2(mhp.x,d3,acc[2][3]);
        acc[3][0]=fma2(mhp.y,d0,acc[3][0]); acc[3][1]=fma2(mhp.y,d1,acc[3][1]); acc[3][2]=fma2(mhp.y,d2,acc[3][2]); acc[3][3]=fma2(mhp.y,d3,acc[3][3]);
        mhi += MST; dp += DST;
    }

    // Per-sample partial quad over this thread's 8 rows (halves = row pair)
    float4 q;
    {
        float* qf = reinterpret_cast<float*>(&q);
        #pragma unroll
        for (int s = 0; s < 4; ++s) {
            ull t = mul2(acc[0][s], acc[0][s]);
            t = fma2(acc[1][s], acc[1][s], t);
            t = fma2(acc[2][s], acc[2][s], t);
            t = fma2(acc[3][s], acc[3][s], t);
            float2 f = asf2(t);
            qf[s] = f.x + f.y;
        }
    }

    __syncthreads();   // ds reads done -> reuse as scratch [ty][s]
    *reinterpret_cast<float4*>(ds + ty * DST + 4 * tx) = q;
    __syncthreads();

    if (tid < ST && tid < navail) {
        float sum = 0.0f;
        #pragma unroll
        for (int t = 0; t < 10; ++t) sum += ds[t * DST + tid];
        float ll = -0.5f * sum - g_logdet[bk] - 0.5f * (float)NDIM * LOG_2PI;
        out[((size_t)b * SEQ + s0 + tid) * KST + k] = ll;
    }
}

// ---------------------------------------------------------------------------
extern "C" void kernel_launch(void* const* d_in, const int* in_sizes, int n_in,
                              void* d_out, int out_size) {
    const float* x     = (const float*)d_in[0];
    const float* mu    = (const float*)d_in[1];
    const float* sigma = (const float*)d_in[2];
    float* out = (float*)d_out;

    const int llsmem = (NDIM * MST + NDIM * DST) * sizeof(float);  // 69120 B
    cudaFuncSetAttribute(ll_kernel, cudaFuncAttributeMaxDynamicSharedMemorySize, llsmem);

    chol_inv_kernel<<<NBK, 96>>>(sigma);

    dim3 grid((SEQ + ST - 1) / ST, KST, BATCH);
    ll_kernel<<<grid, 320, llsmem>>>(x, mu, out);
}

// round 7
// speedup vs baseline: 2.7291x; 1.0588x over previous
#include <cuda_runtime.h>
#include <math.h>

constexpr int NDIM  = 80;
constexpr int BATCH = 64;
constexpr int SEQ   = 1000;
constexpr int KST   = 12;
constexpr int NBK   = BATCH * KST;   // 768
constexpr int ST    = 128;           // samples per block (kernel B)
constexpr int KPB   = 3;             // k's per block
constexpr int KGRP  = KST / KPB;     // 4
constexpr int MST   = 84;            // msh row stride
constexpr int DST   = 132;           // ds row stride
constexpr int AST   = 82;            // chol A row stride

constexpr float LOG_2PI = 1.837877066409345339082f;
constexpr float EPS = 1e-5f;

__device__ float g_minvT[(size_t)NBK * NDIM * NDIM];
__device__ float g_logdet[NBK];
__device__ float g_negc[(size_t)NBK * NDIM];   // -M*mu per (b,k)

typedef unsigned long long ull;
__device__ __forceinline__ ull fma2(ull a, ull b, ull c) {
    ull d; asm("fma.rn.f32x2 %0,%1,%2,%3;" : "=l"(d) : "l"(a), "l"(b), "l"(c)); return d;
}
__device__ __forceinline__ ull mul2(ull a, ull b) {
    ull d; asm("mul.rn.f32x2 %0,%1,%2;" : "=l"(d) : "l"(a), "l"(b)); return d;
}
__device__ __forceinline__ ull add2(ull a, ull b) {
    ull d; asm("add.rn.f32x2 %0,%1,%2;" : "=l"(d) : "l"(a), "l"(b)); return d;
}
__device__ __forceinline__ ull dup2(float x) {
    ull d; asm("mov.b64 %0,{%1,%1};" : "=l"(d) : "f"(x)); return d;
}
__device__ __forceinline__ float2 asf2(ull v) {
    float2 r; asm("mov.b64 {%0,%1},%2;" : "=f"(r.x), "=f"(r.y) : "l"(v)); return r;
}

// ---------------------------------------------------------------------------
// Kernel A: per (b,k). Gauss elimination, scale to L, logdet, sync-free
// triangular inverse into the upper triangle, and c = M*mu (stored negated).
// ---------------------------------------------------------------------------
__global__ __launch_bounds__(96) void chol_inv_kernel(const float* __restrict__ sigma,
                                                      const float* __restrict__ mu) {
    __shared__ __align__(16) float A[NDIM * AST];      // 25.6 KB
    __shared__ __align__(16) float colbuf[NDIM + 2];
    __shared__ float rinv[NDIM];
    __shared__ float lbuf[NDIM];
    __shared__ float mush[NDIM];
    __shared__ float dinvsh;

    const int bk  = blockIdx.x;
    const int tid = threadIdx.x;
    const int i   = tid;
    const float* Sg = sigma + (size_t)bk * NDIM * NDIM;

    for (int idx = tid; idx < NDIM * NDIM; idx += 96) {
        int r = idx / NDIM, c = idx % NDIM;
        float v = Sg[idx];
        if (r == c) v += EPS;
        A[r * AST + c] = v;
    }
    if (tid < NDIM) mush[tid] = mu[(size_t)bk * NDIM + tid];
    __syncthreads();

    for (int k = 0; k < NDIM - 1; ++k) {
        for (int j = tid; j < NDIM; j += 96) colbuf[j] = A[j * AST + k];
        if (tid == 0) dinvsh = 1.0f / A[k * AST + k];
        __syncthreads();
        if (i > k && i < NDIM) {
            float nci = -colbuf[i] * dinvsh;
            float* Ai = A + i * AST;
            int j = k + 1;
            if (j & 1) { Ai[j] = fmaf(nci, colbuf[j], Ai[j]); ++j; }
            ull nci2 = dup2(nci);
            #pragma unroll 4
            for (; j + 1 <= i; j += 2) {
                ull a2 = *reinterpret_cast<ull*>(Ai + j);
                ull c2 = *reinterpret_cast<const ull*>(colbuf + j);
                *reinterpret_cast<ull*>(Ai + j) = fma2(nci2, c2, a2);
            }
            if (j == i) Ai[j] = fmaf(nci, colbuf[j], Ai[j]);
        }
        __syncthreads();
    }

    if (tid < NDIM) {
        float d = A[tid * AST + tid];
        rinv[tid] = 1.0f / sqrtf(d);
        lbuf[tid] = logf(d);
    }
    __syncthreads();
    if (tid == 0) {
        float s = 0.0f;
        for (int j = 0; j < NDIM; ++j) s += lbuf[j];
        g_logdet[bk] = 0.5f * s;
    }
    // Scale lower part to Cholesky L
    if (i < NDIM) {
        float* Ai = A + i * AST;
        int k = 0;
        #pragma unroll 4
        for (; k + 1 <= i - 1; k += 2) {
            ull a2 = *reinterpret_cast<ull*>(Ai + k);
            ull r2 = *reinterpret_cast<const ull*>(rinv + k);
            *reinterpret_cast<ull*>(Ai + k) = mul2(a2, r2);
        }
        if (k <= i - 1) Ai[k] *= rinv[k];
    }
    __syncthreads();

    // Sync-free triangular inverse X = L^-1 into the UPPER triangle (col i private).
    if (i > 0 && i < NDIM) {
        for (int jj = i - 1; jj >= 0; --jj) {
            float s0 = rinv[i] * A[i * AST + jj];
            float s1 = 0.f, s2 = 0.f, s3 = 0.f;
            int k = jj + 1;
            for (; k + 3 < i; k += 4) {
                s0 = fmaf(A[k * AST + i],     A[k * AST + jj],     s0);
                s1 = fmaf(A[(k+1) * AST + i], A[(k+1) * AST + jj], s1);
                s2 = fmaf(A[(k+2) * AST + i], A[(k+2) * AST + jj], s2);
                s3 = fmaf(A[(k+3) * AST + i], A[(k+3) * AST + jj], s3);
            }
            for (; k < i; ++k)
                s0 = fmaf(A[k * AST + i], A[k * AST + jj], s0);
            A[jj * AST + i] = -rinv[jj] * ((s0 + s1) + (s2 + s3));
        }
    }
    __syncthreads();

    // negc[i] = -(X[i][i]*mu[i] + sum_{jj<i} X[i][jj]*mu[jj]);  X[i][jj] at A[jj][i]
    if (i < NDIM) {
        float s = rinv[i] * mush[i];
        for (int jj = 0; jj < i; ++jj)
            s = fmaf(A[jj * AST + i], mush[jj], s);
        g_negc[(size_t)bk * NDIM + i] = -s;
    }

    float* out = g_minvT + (size_t)bk * NDIM * NDIM;
    for (int idx = tid; idx < NDIM * NDIM; idx += 96) {
        int j = idx / NDIM, c = idx % NDIM;
        float v;
        if (c > j)       v = A[j * AST + c];
        else if (c == j) v = rinv[c];
        else             v = 0.0f;
        out[idx] = v;
    }
}

// ---------------------------------------------------------------------------
// Kernel B: block = (s-tile, k-group of 3, b). x staged (transposed) ONCE,
// reused across 3 k's. Per k: stage msh + negc, mainloop (row-paired f32x2,
// d-prefetch), epilogue z = Mx - c, quad, ll.
// 320 threads, 3 blocks/SM. smem = msh 26880 + ds 42240 + red 5280 = 74400 B.
// ---------------------------------------------------------------------------
__global__ __launch_bounds__(320, 3) void ll_kernel(const float* __restrict__ x,
                                                    float* __restrict__ out) {
    extern __shared__ float sm[];
    float* msh = sm;                        // [NDIM][MST]
    float* ds  = sm + NDIM * MST;           // [NDIM][DST]  x transposed [n][s]
    float* red = ds + NDIM * DST;           // [10][DST]    reduction scratch

    const int tid = threadIdx.x;
    const int tx  = tid & 31;
    const int ty  = tid >> 5;               // warp id 0..9
    const int s0  = blockIdx.x * ST;
    const int kg  = blockIdx.y;             // k-group
    const int b   = blockIdx.z;

    int navail = SEQ - s0; if (navail > ST) navail = ST;
    const float* xb = x + ((size_t)b * SEQ + s0) * NDIM;

    // Stage x transposed: ds[n][s] = x[b][s0+s][n]. Lanes dense in s ->
    // conflict-free STS; gmem reads strided float4 (L2-cached tile).
    for (int t = tid; t < (NDIM / 4) * ST; t += 320) {
        int n4 = t / ST;                    // 0..19
        int s  = t - n4 * ST;               // lanes dense in s
        float4 v = make_float4(0.f, 0.f, 0.f, 0.f);
        if (s < navail)
            v = *reinterpret_cast<const float4*>(xb + (size_t)s * NDIM + 4 * n4);
        ds[(4 * n4 + 0) * DST + s] = v.x;
        ds[(4 * n4 + 1) * DST + s] = v.y;
        ds[(4 * n4 + 2) * DST + s] = v.z;
        ds[(4 * n4 + 3) * DST + s] = v.w;
    }

    const int rlo = 4 * ty;
    const int rhi = 76 - 4 * ty;
    const int jA  = rlo + 4;
    const int jB  = 80 - rlo;

    for (int kk = 0; kk < KPB; ++kk) {
        const int k  = kg * KPB + kk;
        const int bk = b * KST + k;

        // Stage MinvT (coalesced LDG, conflict-free STS) + negc into red tail
        __syncthreads();   // prior-k red reads / first-pass ds writes complete
        const float* mv = g_minvT + (size_t)bk * NDIM * NDIM;
        for (int idx = tid; idx < NDIM * NDIM; idx += 320) {
            int j = idx / NDIM, i2 = idx - j * NDIM;
            msh[j * MST + i2] = __ldg(mv + idx);
        }
        float* ncsh = red + DST;            // 80 floats, after row-0 scratch
        if (tid < NDIM) ncsh[tid] = __ldg(g_negc + (size_t)bk * NDIM + tid);
        __syncthreads();

        ull acc[4][4];
        #pragma unroll
        for (int p = 0; p < 4; ++p)
            #pragma unroll
            for (int s = 0; s < 4; ++s) acc[p][s] = 0ULL;

        const float* mlo = msh + rlo;
        const float* mhi = msh + rhi;
        const float* dp  = ds + 4 * tx;
        float4 d4 = *reinterpret_cast<const float4*>(dp);
        dp += DST;

        #pragma unroll 2
        for (int j = 0; j < jA; ++j) {
            ulonglong2 mlp = *reinterpret_cast<const ulonglong2*>(mlo);
            ulonglong2 mhp = *reinterpret_cast<const ulonglong2*>(mhi);
            float4 dn = *reinterpret_cast<const float4*>(dp);   // prefetch next j
            ull d0 = dup2(d4.x), d1 = dup2(d4.y), d2 = dup2(d4.z), d3 = dup2(d4.w);
            acc[0][0]=fma2(mlp.x,d0,acc[0][0]); acc[0][1]=fma2(mlp.x,d1,acc[0][1]); acc[0][2]=fma2(mlp.x,d2,acc[0][2]); acc[0][3]=fma2(mlp.x,d3,acc[0][3]);
            acc[1][0]=fma2(mlp.y,d0,acc[1][0]); acc[1][1]=fma2(mlp.y,d1,acc[1][1]); acc[1][2]=fma2(mlp.y,d2,acc[1][2]); acc[1][3]=fma2(mlp.y,d3,acc[1][3]);
            acc[2][0]=fma2(mhp.x,d0,acc[2][0]); acc[2][1]=fma2(mhp.x,d1,acc[2][1]); acc[2][2]=fma2(mhp.x,d2,acc[2][2]); acc[2][3]=fma2(mhp.x,d3,acc[2][3]);
            acc[3][0]=fma2(mhp.y,d0,acc[3][0]); acc[3][1]=fma2(mhp.y,d1,acc[3][1]); acc[3][2]=fma2(mhp.y,d2,acc[3][2]); acc[3][3]=fma2(mhp.y,d3,acc[3][3]);
            d4 = dn; mlo += MST; mhi += MST; dp += DST;
        }
        #pragma unroll 4
        for (int j = jA; j < jB; ++j) {
            ulonglong2 mhp = *reinterpret_cast<const ulonglong2*>(mhi);
            float4 dn = *reinterpret_cast<const float4*>(dp);   // last lands in red (safe)
            ull d0 = dup2(d4.x), d1 = dup2(d4.y), d2 = dup2(d4.z), d3 = dup2(d4.w);
            acc[2][0]=fma2(mhp.x,d0,acc[2][0]); acc[2][1]=fma2(mhp.x,d1,acc[2][1]); acc[2][2]=fma2(mhp.x,d2,acc[2][2]); acc[2][3]=fma2(mhp.x,d3,acc[2][3]);
            acc[3][0]=fma2(mhp.y,d0,acc[3][0]); acc[3][1]=fma2(mhp.y,d1,acc[3][1]); acc[3][2]=fma2(mhp.y,d2,acc[3][2]); acc[3][3]=fma2(mhp.y,d3,acc[3][3]);
            d4 = dn; mhi += MST; dp += DST;
        }

        // Epilogue: z = acc - c (f32x2), quad partial per sample
        ull ncl0 = *reinterpret_cast<const ull*>(ncsh + rlo);
        ull ncl1 = *reinterpret_cast<const ull*>(ncsh + rlo + 2);
        ull nch0 = *reinterpret_cast<const ull*>(ncsh + rhi);
        ull nch1 = *reinterpret_cast<const ull*>(ncsh + rhi + 2);
        float4 q;
        float* qf = reinterpret_cast<float*>(&q);
        #pragma unroll
        for (int s = 0; s < 4; ++s) {
            ull z0 = add2(acc[0][s], ncl0);
            ull z1 = add2(acc[1][s], ncl1);
            ull z2 = add2(acc[2][s], nch0);
            ull z3 = add2(acc[3][s], nch1);
            ull t = mul2(z0, z0);
            t = fma2(z1, z1, t);
            t = fma2(z2, z2, t);
            t = fma2(z3, z3, t);
            float2 f = asf2(t);
            qf[s] = f.x + f.y;
        }

        __syncthreads();   // ncsh reads done; red row-0 prefetch garbage done
        *reinterpret_cast<float4*>(red + ty * DST + 4 * tx) = q;
        __syncthreads();

        if (tid < ST && tid < navail) {
            float sum = 0.0f;
            #pragma unroll
            for (int t = 0; t < 10; ++t) sum += red[t * DST + tid];
            float ll = -0.5f * sum - __ldg(g_logdet + bk) - 0.5f * (float)NDIM * LOG_2PI;
            out[((size_t)b * SEQ + s0 + tid) * KST + k] = ll;
        }
    }
}

// ---------------------------------------------------------------------------
extern "C" void kernel_launch(void* const* d_in, const int* in_sizes, int n_in,
                              void* d_out, int out_size) {
    const float* x     = (const float*)d_in[0];
    const float* mu    = (const float*)d_in[1];
    const float* sigma = (const float*)d_in[2];
    float* out = (float*)d_out;

    const int llsmem = (NDIM * MST + NDIM * DST + 10 * DST) * sizeof(float);  // 74400 B
    cudaFuncSetAttribute(ll_kernel, cudaFuncAttributeMaxDynamicSharedMemorySize, llsmem);

    chol_inv_kernel<<<NBK, 96>>>(sigma, mu);

    dim3 grid((SEQ + ST - 1) / ST, KGRP, BATCH);
    ll_kernel<<<grid, 320, llsmem>>>(x, out);
}